// round 11
// baseline (speedup 1.0000x reference)
#include <cuda_runtime.h>
#include <stdint.h>

// out[n,o] = -|eta| * sum_k |x[n,k] - w[o,k]|
// N=2048, K=1024, O=2048, fp32.
//
// Round 11: dual-pipe split. Per 32-k tile: 24 k's run int32 SAD
// (alu pipe, 1 issue/elem, fixed-point 2^16), 8 k's run float
// d=x-w; acc+=|d| (fma pipe, 2 issues/elem, |.| is a free SASS operand
// modifier). Warps process the 8 bodies of each tile in rotated order so
// at any instant ~3/4 of warps feed the alu pipe and ~1/4 the fma pipe.
// cp.async double-buffered 64x64 tiles, 3 CTAs/SM.

#define N_ROWS 2048
#define K_DIM  1024
#define O_COLS 2048

#define TN 64
#define TO 64
#define KT 32
#define SS 36                        // row stride (4B words); conflict-free
#define NTILES (K_DIM / KT)          // 32
#define BUF_WORDS ((TN + TO) * SS)   // 4608 words = 18432 B per buffer

#define QSCALE 65536.0f
#define QINV   (1.0f / 65536.0f)

__device__ int g_qx[N_ROWS * K_DIM];   // 8 MB
__device__ int g_qw[O_COLS * K_DIM];   // 8 MB

// quantize x (first half of blocks) and w (second half), 1 float4/thread
__global__ void quant_kernel(const float* __restrict__ x,
                             const float* __restrict__ w)
{
    int b = blockIdx.x;
    bool is_x = b < (N_ROWS * K_DIM / 1024);
    int idx = (is_x ? b : b - N_ROWS * K_DIM / 1024) * 256 + threadIdx.x;
    const float4* src = (const float4*)(is_x ? x : w);
    int4* dst = (int4*)(is_x ? g_qx : g_qw);
    float4 v = src[idx];
    int4 q;
    q.x = __float2int_rn(v.x * QSCALE);
    q.y = __float2int_rn(v.y * QSCALE);
    q.z = __float2int_rn(v.z * QSCALE);
    q.w = __float2int_rn(v.w * QSCALE);
    dst[idx] = q;
}

__device__ __forceinline__ void cp16(int* dst, const void* src)
{
    unsigned s = (unsigned)__cvta_generic_to_shared(dst);
    asm volatile("cp.async.cg.shared.global [%0], [%1], 16;"
                 :: "r"(s), "l"(src) : "memory");
}
__device__ __forceinline__ void cp_commit()
{
    asm volatile("cp.async.commit_group;" ::: "memory");
}
__device__ __forceinline__ void cp_wait_all()
{
    asm volatile("cp.async.wait_group 0;" ::: "memory");
}

__global__ __launch_bounds__(256, 3)
void adder_linear_kernel(const float* __restrict__ x,
                         const float* __restrict__ w,
                         const float* __restrict__ eta,
                         float* __restrict__ out)
{
    __shared__ int smem[2 * BUF_WORDS];   // 36864 B -> 3 CTAs/SM

    const int tid    = threadIdx.x;
    const int wid    = tid >> 5;
    const int lane   = tid & 31;
    const int warp_n = wid & 1;          // 0..1
    const int warp_o = wid >> 1;         // 0..3
    const int lane_n = lane & 7;         // 0..7
    const int lane_o = lane >> 3;        // 0..3

    const int n0 = blockIdx.y * TN;
    const int o0 = blockIdx.x * TO;

    // thread outputs: n = n0 + tn + i*8 (i<4), o = o0 + to + j*4 (j<4)
    const int tn = warp_n * 32 + lane_n;
    const int to = warp_o * 16 + lane_o;

    // per-warp body rotation (decorrelate pipe phases across warps/CTAs)
    const int rot = (wid * 3 + blockIdx.x + blockIdx.y * 3) & 7;

    unsigned int iacc[4][4];
    float        facc[4][4];
    #pragma unroll
    for (int i = 0; i < 4; i++)
        #pragma unroll
        for (int j = 0; j < 4; j++) {
            iacc[i][j] = 0u;
            facc[i][j] = 0.0f;
        }

    // chunks q=0..5 -> int (g_qx/g_qw, k offset q*4 in [0,24))
    // chunks q=6..7 -> float bits (x/w, k offset q*4 in [24,32))
    auto prefetch = [&](int* buf, int kt) {
        int* sxp = buf;
        int* swp = buf + TN * SS;
        #pragma unroll
        for (int it = 0; it < 2; it++) {
            int idx = tid + 256 * it;          // 0..511
            int r = idx >> 3, q = idx & 7;
            size_t off = (size_t)(n0 + r) * K_DIM + kt + q * 4;
            const void* src = (q < 6) ? (const void*)(g_qx + off)
                                      : (const void*)(x + off);
            cp16(&sxp[r * SS + q * 4], src);
        }
        #pragma unroll
        for (int it = 0; it < 2; it++) {
            int idx = tid + 256 * it;
            int r = idx >> 3, q = idx & 7;
            size_t off = (size_t)(o0 + r) * K_DIM + kt + q * 4;
            const void* src = (q < 6) ? (const void*)(g_qw + off)
                                      : (const void*)(w + off);
            cp16(&swp[r * SS + q * 4], src);
        }
    };

    prefetch(smem, 0);
    cp_commit();

    for (int t = 0; t < NTILES; t++) {
        cp_wait_all();          // tile t landed
        __syncthreads();        // other buffer free for refill

        if (t + 1 < NTILES) {
            prefetch((t & 1) ? smem : smem + BUF_WORDS, (t + 1) * KT);
            cp_commit();
        }

        const int* sb = (t & 1) ? smem + BUF_WORDS : smem;
        const int* xb = sb + tn * SS;
        const int* wb = sb + TN * SS + to * SS;

        #pragma unroll
        for (int bb = 0; bb < 8; bb++) {
            const int b  = (bb + rot) & 7;
            const int kk = b * 4;
            if (b < 6) {
                // ---- int body: 4 k, 64 SAD (alu pipe) ----
                int4 wq[4], xq[4];
                #pragma unroll
                for (int j = 0; j < 4; j++)
                    wq[j] = *(const int4*)(wb + j * 4 * SS + kk);
                #pragma unroll
                for (int i = 0; i < 4; i++)
                    xq[i] = *(const int4*)(xb + i * 8 * SS + kk);

                #pragma unroll
                for (int i = 0; i < 4; i++)
                    #pragma unroll
                    for (int j = 0; j < 4; j++)
                        iacc[i][j] = __sad(xq[i].x, wq[j].x, iacc[i][j]);
                #pragma unroll
                for (int i = 0; i < 4; i++)
                    #pragma unroll
                    for (int j = 0; j < 4; j++)
                        iacc[i][j] = __sad(xq[i].y, wq[j].y, iacc[i][j]);
                #pragma unroll
                for (int i = 0; i < 4; i++)
                    #pragma unroll
                    for (int j = 0; j < 4; j++)
                        iacc[i][j] = __sad(xq[i].z, wq[j].z, iacc[i][j]);
                #pragma unroll
                for (int i = 0; i < 4; i++)
                    #pragma unroll
                    for (int j = 0; j < 4; j++)
                        iacc[i][j] = __sad(xq[i].w, wq[j].w, iacc[i][j]);
            } else {
                // ---- float body: 4 k, 128 FADD (fma pipe) ----
                float4 wf[4], xf[4];
                #pragma unroll
                for (int j = 0; j < 4; j++)
                    wf[j] = *(const float4*)(wb + j * 4 * SS + kk);
                #pragma unroll
                for (int i = 0; i < 4; i++)
                    xf[i] = *(const float4*)(xb + i * 8 * SS + kk);

                #pragma unroll
                for (int i = 0; i < 4; i++)
                    #pragma unroll
                    for (int j = 0; j < 4; j++)
                        facc[i][j] += fabsf(xf[i].x - wf[j].x);
                #pragma unroll
                for (int i = 0; i < 4; i++)
                    #pragma unroll
                    for (int j = 0; j < 4; j++)
                        facc[i][j] += fabsf(xf[i].y - wf[j].y);
                #pragma unroll
                for (int i = 0; i < 4; i++)
                    #pragma unroll
                    for (int j = 0; j < 4; j++)
                        facc[i][j] += fabsf(xf[i].z - wf[j].z);
                #pragma unroll
                for (int i = 0; i < 4; i++)
                    #pragma unroll
                    for (int j = 0; j < 4; j++)
                        facc[i][j] += fabsf(xf[i].w - wf[j].w);
            }
        }
    }

    const float meta = -fabsf(eta[0]);

    #pragma unroll
    for (int i = 0; i < 4; i++) {
        int n = n0 + tn + i * 8;
        #pragma unroll
        for (int j = 0; j < 4; j++) {
            int o = o0 + to + j * 4;
            float S = fmaf((float)iacc[i][j], QINV, facc[i][j]);
            out[(size_t)n * O_COLS + o] = meta * S;
        }
    }
}

extern "C" void kernel_launch(void* const* d_in, const int* in_sizes, int n_in,
                              void* d_out, int out_size)
{
    const float* x   = (const float*)d_in[0];   // [2048, 1024]
    const float* w   = (const float*)d_in[1];   // [2048, 1024]
    const float* eta = (const float*)d_in[2];   // [1]
    float* out = (float*)d_out;                 // [2048, 2048]

    quant_kernel<<<(N_ROWS + O_COLS) * K_DIM / 1024, 256>>>(x, w);

    dim3 grid(O_COLS / TO, N_ROWS / TN);        // (32, 32) = 1024 blocks
    adder_linear_kernel<<<grid, 256>>>(x, w, eta, out);
}